// round 13
// baseline (speedup 1.0000x reference)
#include <cuda_runtime.h>
#include <math.h>

// Fixed shapes per reference
#define N_PTS 262144
#define B_ 4
#define T_ 4
#define P_ 512
#define R_ 256
#define C_ 64
#define H_ 512
#define W_ 512
#define HW_ (H_ * W_)
#define RC_ (R_ * C_)
#define PRC_ (P_ * RC_)

#define SCATTER_BLOCKS 16384               // 16 points per 256-thr block
#define COPY_BLOCKS 16384
#define MIX_BLOCKS 24576                   // first region: 2 scatter : 1 copy
#define EPI_BLOCKS 512
#define TOTAL_BLOCKS (MIX_BLOCKS + 8192 + EPI_BLOCKS)  // 33280
#define SCRATCH_ELEMS (B_ * H_ * T_ * C_)  // 524288 floats (2MB, L2-resident)

// Privatized accumulator [b][y][t][c] (channel-contiguous -> coalesced REDs).
// BSS zero-init; epilogue re-zeros after consuming (invariant across replays).
__device__ float g_scratch[SCRATCH_ELEMS];
__device__ unsigned int g_done;      // scatter blocks completed
__device__ unsigned int g_epi_done;  // epilogue blocks completed (for reset)

__device__ __forceinline__ void red_add_v4(float* p, float4 v) {
    asm volatile("red.global.add.v4.f32 [%0], {%1,%2,%3,%4};"
                 :: "l"(p), "f"(v.x), "f"(v.y), "f"(v.z), "f"(v.w)
                 : "memory");
}

// Streaming 32B copy with L2 evict_first (zero-reuse stream; keep L2 for the
// pview gather working set). ptxas requires .v4.b64 width for the modifier.
__device__ __forceinline__ ulonglong4 ld_stream32(const ulonglong4* p) {
    ulonglong4 v;
    asm volatile("ld.global.nc.L2::evict_first.v4.b64 {%0,%1,%2,%3}, [%4];"
                 : "=l"(v.x), "=l"(v.y), "=l"(v.z), "=l"(v.w) : "l"(p));
    return v;
}
__device__ __forceinline__ void st_stream32(ulonglong4* p, ulonglong4 v) {
    asm volatile("st.global.L2::evict_first.v4.b64 [%0], {%1,%2,%3,%4};"
                 :: "l"(p), "l"(v.x), "l"(v.y), "l"(v.z), "l"(v.w)
                 : "memory");
}

// ONE kernel, three roles:
//  - blocks [0, 24576): pattern [copy, scatter, scatter] -> all 16384 scatter
//    blocks finish ~75% into the kernel while staying interleaved with copy
//    traffic (DRAM saturated by the stream, gathers ride along).
//  - blocks [24576, 32768): pure copy tail.
//  - blocks [32768, 33280): epilogue. Spin until all scatter blocks published
//    their reds, then write the "hole" quads out[b][c][y][0..3] =
//    spatial + scratch NON-atomically, overlapped with the copy tail.
//    Disjointness: the copy path skips exactly those quads.
__global__ void __launch_bounds__(256) pp_mega_kernel(
    const int4*  __restrict__ coords,
    const float* __restrict__ pview,
    const ulonglong4* __restrict__ spatial32,
    ulonglong4* __restrict__ out32)
{
    const int tid = threadIdx.x;
    const int bid = blockIdx.x;

    int role;          // 0 = copy, 1 = scatter, 2 = epilogue
    int work_id;
    if (bid < MIX_BLOCKS) {
        const int q = bid / 3, m = bid - q * 3;
        if (m == 0) { role = 0; work_id = q; }              // 8192 copies
        else        { role = 1; work_id = q * 2 + m - 1; }  // 16384 scatters
    } else if (bid < MIX_BLOCKS + 8192) {
        role = 0; work_id = 8192 + (bid - MIX_BLOCKS);      // 8192 copies
    } else {
        role = 2; work_id = bid - (MIX_BLOCKS + 8192);      // 512 epilogue
    }

    if (role == 0) {
        // ---- copy path: 256MB in 32B chunks, skipping the hole quads ----
        // Hole = first 16B of each 2KB out row = first half of chunks with
        // (idx % 64 == 0). For those, copy only the second 16B.
        int idx = work_id * 256 + tid;
        const int stride = COPY_BLOCKS * 256;          // 4194304 chunks/iter
        #pragma unroll
        for (int i = 0; i < 2; i++) {
            if ((idx & 63) != 0) {
                st_stream32(out32 + idx, ld_stream32(spatial32 + idx));
            } else {
                const float4* s = (const float4*)(spatial32 + idx);
                float4* d = (float4*)(out32 + idx);
                d[1] = s[1];                           // second 16B only
            }
            idx += stride;
        }
        return;
    }

    if (role == 1) {
        // ---- scatter path: 16 lanes per point, float4 per lane ----
        const int warp   = tid >> 5;
        const int half   = (tid >> 4) & 1;
        const int lane16 = tid & 15;
        const int pt = work_id * 16 + warp * 2 + half;

        int4 c = coords[pt];
        const int b = c.x, t = c.y, yy = c.z, xx = c.w;

        // Replicate reference f32 math exactly (no FMA contraction) so the
        // xf==0 special case matches bit-for-bit.
        float yf = __fadd_rn(__fmul_rn((float)yy, 0.2f), -51.2f);
        float xf = __fadd_rn(__fmul_rn((float)xx, 0.2f), -51.2f);

        float r = sqrtf(__fadd_rn(__fmul_rn(xf, xf), __fmul_rn(yf, yf)));
        float psi;
        if (xf == 0.0f && yf >= 0.0f) {
            psi = 1.57079632679489662f;   // pi/2
        } else {
            psi = atan2f(yf, xf);
        }

        float r_idx = __fdiv_rn(r, 0.3f);
        float p_idx = __fdiv_rn(__fadd_rn(psi, 3.14159265358979323846f),
                                0.012566370614359172f);

        int r0i = (int)floorf(r_idx);
        int p0i = (int)floorf(p_idx);
        // t frac is exactly 0 -> t+1 corner weight == 0, skipped.

        const float fr = r_idx - (float)r0i;
        const float fp = p_idx - (float)p0i;

        const int r0 = r0i * C_;
        const int r1 = min(r0i + 1, R_ - 1) * C_;
        const int p0 = p0i * RC_;
        const int p1 = min(p0i + 1, P_ - 1) * RC_;

        const float* base = pview + (b * T_ + t) * PRC_ + 4 * lane16;

        float4 v00 = *(const float4*)(base + p0 + r0);
        float4 v01 = *(const float4*)(base + p0 + r1);
        float4 v10 = *(const float4*)(base + p1 + r0);
        float4 v11 = *(const float4*)(base + p1 + r1);

        const float wr0 = 1.0f - fr, wr1 = fr;
        const float wp0 = 1.0f - fp, wp1 = fp;

        float4 acc;
        acc.x = wp0 * (wr0 * v00.x + wr1 * v01.x) + wp1 * (wr0 * v10.x + wr1 * v11.x);
        acc.y = wp0 * (wr0 * v00.y + wr1 * v01.y) + wp1 * (wr0 * v10.y + wr1 * v11.y);
        acc.z = wp0 * (wr0 * v00.z + wr1 * v01.z) + wp1 * (wr0 * v10.z + wr1 * v11.z);
        acc.w = wp0 * (wr0 * v00.w + wr1 * v01.w) + wp1 * (wr0 * v10.w + wr1 * v11.w);

        float* dst = g_scratch + ((b * H_ + yy) * T_ + t) * C_ + 4 * lane16;
        red_add_v4(dst, acc);

        // Publish: reds ordered before the counter bump.
        __threadfence();
        __syncthreads();
        if (tid == 0) atomicAdd(&g_done, 1u);
        return;
    }

    // ---- epilogue (in-grid, overlapped with the pure-copy tail) ----
    if (tid == 0) {
        while (*(volatile unsigned int*)&g_done < SCATTER_BLOCKS)
            __nanosleep(128);
    }
    __syncthreads();
    __threadfence();   // acquire: scratch reds visible

    const int idx = work_id * 256 + tid;               // (b, y, c) flat
    const int ch = idx & (C_ - 1);
    const int y  = (idx >> 6) & (H_ - 1);
    const int b  = idx >> 15;

    const int sbase = ((b * H_ + y) * T_) * C_ + ch;   // t stride = C_
    float v0 = g_scratch[sbase];
    float v1 = g_scratch[sbase + C_];
    float v2 = g_scratch[sbase + 2 * C_];
    float v3 = g_scratch[sbase + 3 * C_];

    g_scratch[sbase]          = 0.0f;                  // re-zero for next replay
    g_scratch[sbase + C_]     = 0.0f;
    g_scratch[sbase + 2 * C_] = 0.0f;
    g_scratch[sbase + 3 * C_] = 0.0f;

    // Hole quad this thread owns: out[b][ch][y][0..3] (float4 index)
    const int hole = (b * (C_ * HW_) + ch * HW_ + y * W_) >> 2;
    const float4* sp4 = (const float4*)spatial32;
    float4 s = sp4[hole];
    s.x += v0; s.y += v1; s.z += v2; s.w += v3;
    ((float4*)out32)[hole] = s;                        // non-atomic, disjoint

    // Self-reset counters (last epilogue block) for graph-replay determinism.
    __syncthreads();
    if (tid == 0) {
        unsigned int prev = atomicAdd(&g_epi_done, 1u);
        if (prev == EPI_BLOCKS - 1) {
            g_done = 0u;
            g_epi_done = 0u;
            __threadfence();
        }
    }
}

extern "C" void kernel_launch(void* const* d_in, const int* in_sizes, int n_in,
                              void* d_out, int out_size) {
    const int*   coords  = (const int*)d_in[0];   // voxel_coords [N,4] int32
    const float* pview   = (const float*)d_in[1]; // [B,T,P,R,C] f32
    const float* spatial = (const float*)d_in[2]; // [B,C,H,W] f32
    float* out = (float*)d_out;

    pp_mega_kernel<<<TOTAL_BLOCKS, 256>>>(
        (const int4*)coords, pview, (const ulonglong4*)spatial, (ulonglong4*)out);
}

// round 14
// speedup vs baseline: 1.0228x; 1.0228x over previous
#include <cuda_runtime.h>
#include <math.h>

// Fixed shapes per reference
#define N_PTS 262144
#define B_ 4
#define T_ 4
#define P_ 512
#define R_ 256
#define C_ 64
#define H_ 512
#define W_ 512
#define HW_ (H_ * W_)
#define RC_ (R_ * C_)
#define PRC_ (P_ * RC_)

#define COPY_BLOCKS 16384
#define SCATTER_BLOCKS (N_PTS / 16)       // 16384: 16 points per 256-thr block
#define EPI_BLOCKS 512
#define SCRATCH_ELEMS (B_ * H_ * T_ * C_) // 524288 floats (2MB, L2-resident)

// Privatized accumulator [b][y][t][c] (channel-contiguous -> coalesced REDs).
// BSS zero-init; epilogue re-zeros after consuming (invariant across replays).
__device__ float g_scratch[SCRATCH_ELEMS];

__device__ __forceinline__ void red_add_v4(float* p, float4 v) {
    asm volatile("red.global.add.v4.f32 [%0], {%1,%2,%3,%4};"
                 :: "l"(p), "f"(v.x), "f"(v.y), "f"(v.z), "f"(v.w)
                 : "memory");
}

// Streaming 32B copy with L2 evict_first (zero-reuse stream; keep L2 for the
// pview gather working set). ptxas requires .v4.b64 width for the modifier.
__device__ __forceinline__ ulonglong4 ld_stream32(const ulonglong4* p) {
    ulonglong4 v;
    asm volatile("ld.global.nc.L2::evict_first.v4.b64 {%0,%1,%2,%3}, [%4];"
                 : "=l"(v.x), "=l"(v.y), "=l"(v.z), "=l"(v.w) : "l"(p));
    return v;
}
__device__ __forceinline__ void st_stream32(ulonglong4* p, ulonglong4 v) {
    asm volatile("st.global.L2::evict_first.v4.b64 [%0], {%1,%2,%3,%4};"
                 :: "l"(p), "l"(v.x), "l"(v.y), "l"(v.z), "l"(v.w)
                 : "memory");
}

// Copy kernel: 256MB out = spatial in 32B chunks, SKIPPING the hole quads
// out[b][c][y][0..3] (= first 16B of each 2KB out row; chunk idx%64==0).
// The epilogue kernel owns those quads (runs concurrently on another stream,
// addresses disjoint -> no race, no atomics).
__global__ void __launch_bounds__(256) pp_copy_kernel(
    const ulonglong4* __restrict__ spatial32,
    ulonglong4* __restrict__ out32)
{
    int idx = blockIdx.x * 256 + threadIdx.x;
    const int stride = COPY_BLOCKS * 256;          // 4194304 chunks per iter
    #pragma unroll
    for (int i = 0; i < 2; i++) {
        if ((idx & 63) != 0) {
            st_stream32(out32 + idx, ld_stream32(spatial32 + idx));
        } else {
            // hole chunk: copy only the second 16B (floats 4..7 of the row)
            const float4* s = (const float4*)(spatial32 + idx);
            float4* d = (float4*)(out32 + idx);
            d[1] = s[1];
        }
        idx += stride;
    }
}

// Scatter kernel: 16 lanes per point, float4 per lane; coalesced red.v4 into
// the 2MB L2-resident scratch.
__global__ void __launch_bounds__(256) pp_scatter_kernel(
    const int4*  __restrict__ coords,
    const float* __restrict__ pview)
{
    const int tid = threadIdx.x;
    const int warp   = tid >> 5;
    const int half   = (tid >> 4) & 1;
    const int lane16 = tid & 15;
    const int pt = blockIdx.x * 16 + warp * 2 + half;

    int4 c = coords[pt];
    const int b = c.x, t = c.y, yy = c.z, xx = c.w;

    // Replicate reference f32 math exactly (no FMA contraction) so the
    // xf==0 special case matches bit-for-bit.
    float yf = __fadd_rn(__fmul_rn((float)yy, 0.2f), -51.2f);
    float xf = __fadd_rn(__fmul_rn((float)xx, 0.2f), -51.2f);

    float r = sqrtf(__fadd_rn(__fmul_rn(xf, xf), __fmul_rn(yf, yf)));
    float psi;
    if (xf == 0.0f && yf >= 0.0f) {
        psi = 1.57079632679489662f;       // pi/2
    } else {
        psi = atan2f(yf, xf);
    }

    float r_idx = __fdiv_rn(r, 0.3f);
    float p_idx = __fdiv_rn(__fadd_rn(psi, 3.14159265358979323846f),
                            0.012566370614359172f);

    int r0i = (int)floorf(r_idx);
    int p0i = (int)floorf(p_idx);
    // t frac is exactly 0 (integer cast to float) -> t+1 corner weight == 0.

    const float fr = r_idx - (float)r0i;
    const float fp = p_idx - (float)p0i;

    const int r0 = r0i * C_;
    const int r1 = min(r0i + 1, R_ - 1) * C_;
    const int p0 = p0i * RC_;
    const int p1 = min(p0i + 1, P_ - 1) * RC_;

    const float* base = pview + (b * T_ + t) * PRC_ + 4 * lane16;

    float4 v00 = *(const float4*)(base + p0 + r0);
    float4 v01 = *(const float4*)(base + p0 + r1);
    float4 v10 = *(const float4*)(base + p1 + r0);
    float4 v11 = *(const float4*)(base + p1 + r1);

    const float wr0 = 1.0f - fr, wr1 = fr;
    const float wp0 = 1.0f - fp, wp1 = fp;

    float4 acc;
    acc.x = wp0 * (wr0 * v00.x + wr1 * v01.x) + wp1 * (wr0 * v10.x + wr1 * v11.x);
    acc.y = wp0 * (wr0 * v00.y + wr1 * v01.y) + wp1 * (wr0 * v10.y + wr1 * v11.y);
    acc.z = wp0 * (wr0 * v00.z + wr1 * v01.z) + wp1 * (wr0 * v10.z + wr1 * v11.z);
    acc.w = wp0 * (wr0 * v00.w + wr1 * v01.w) + wp1 * (wr0 * v10.w + wr1 * v11.w);

    float* dst = g_scratch + ((b * H_ + yy) * T_ + t) * C_ + 4 * lane16;
    red_add_v4(dst, acc);
}

// Epilogue: one thread per (b, y, c); writes the hole quad NON-atomically:
// out[b][ch][y][0..3] = spatial + scratch. Runs after scatter (same stream),
// concurrently with the copy kernel (disjoint addresses). Re-zeros scratch.
__global__ void __launch_bounds__(256) pp_epi_kernel(
    const float4* __restrict__ spatial4,
    float4* __restrict__ out4)
{
    const int idx = blockIdx.x * 256 + threadIdx.x;  // (b, y, c) flat
    const int ch = idx & (C_ - 1);
    const int y  = (idx >> 6) & (H_ - 1);
    const int b  = idx >> 15;

    const int sbase = ((b * H_ + y) * T_) * C_ + ch;   // t stride = C_
    float v0 = g_scratch[sbase];
    float v1 = g_scratch[sbase + C_];
    float v2 = g_scratch[sbase + 2 * C_];
    float v3 = g_scratch[sbase + 3 * C_];

    g_scratch[sbase]          = 0.0f;
    g_scratch[sbase + C_]     = 0.0f;
    g_scratch[sbase + 2 * C_] = 0.0f;
    g_scratch[sbase + 3 * C_] = 0.0f;

    const int hole = (b * (C_ * HW_) + ch * HW_ + y * W_) >> 2;
    float4 s = spatial4[hole];
    s.x += v0; s.y += v1; s.z += v2; s.w += v3;
    out4[hole] = s;
}

extern "C" void kernel_launch(void* const* d_in, const int* in_sizes, int n_in,
                              void* d_out, int out_size) {
    const int*   coords  = (const int*)d_in[0];   // voxel_coords [N,4] int32
    const float* pview   = (const float*)d_in[1]; // [B,T,P,R,C] f32
    const float* spatial = (const float*)d_in[2]; // [B,C,H,W] f32
    float* out = (float*)d_out;

    // Fork a side stream inside the capture: copy runs on stream 0,
    // scatter->epilogue on s2, concurrently; join before returning.
    // (Stream/event creation is host-side only — no device memory.)
    cudaStream_t s2;
    cudaStreamCreateWithFlags(&s2, cudaStreamNonBlocking);
    cudaEvent_t ev_fork, ev_join;
    cudaEventCreateWithFlags(&ev_fork, cudaEventDisableTiming);
    cudaEventCreateWithFlags(&ev_join, cudaEventDisableTiming);

    cudaEventRecord(ev_fork, 0);
    cudaStreamWaitEvent(s2, ev_fork, 0);

    pp_copy_kernel<<<COPY_BLOCKS, 256, 0, 0>>>(
        (const ulonglong4*)spatial, (ulonglong4*)out);

    pp_scatter_kernel<<<SCATTER_BLOCKS, 256, 0, s2>>>(
        (const int4*)coords, pview);
    pp_epi_kernel<<<EPI_BLOCKS, 256, 0, s2>>>(
        (const float4*)spatial, (float4*)out);

    cudaEventRecord(ev_join, s2);
    cudaStreamWaitEvent(0, ev_join, 0);
}

// round 15
// speedup vs baseline: 1.0818x; 1.0577x over previous
#include <cuda_runtime.h>
#include <math.h>

// Fixed shapes per reference
#define N_PTS 262144
#define B_ 4
#define T_ 4
#define P_ 512
#define R_ 256
#define C_ 64
#define H_ 512
#define W_ 512
#define HW_ (H_ * W_)
#define RC_ (R_ * C_)
#define PRC_ (P_ * RC_)

#define COPY_BLOCKS 16384
#define SCATTER_BLOCKS (N_PTS / 16)       // 16384: 16 points per 256-thr block
#define SCRATCH_ELEMS (B_ * H_ * T_ * C_) // 524288 floats (2MB, L2-resident)

// Privatized accumulator [b][y][t][c] (channel-contiguous -> coalesced REDs).
// BSS zero-init; epilogue re-zeros after consuming (invariant across replays).
__device__ float g_scratch[SCRATCH_ELEMS];

// Plain v4 reduction (used for out, where L2 residency doesn't matter).
__device__ __forceinline__ void red_add_v4(float* p, float4 v) {
    asm volatile("red.global.add.v4.f32 [%0], {%1,%2,%3,%4};"
                 :: "l"(p), "f"(v.x), "f"(v.y), "f"(v.z), "f"(v.w)
                 : "memory");
}

// v4 reduction with L2 evict_last policy: pins the 2MB scratch in L2 so the
// epilogue's scratch reads hit L2 instead of DRAM (the ~200MB gather stream
// otherwise washes the default-priority scratch lines out).
__device__ __forceinline__ void red_add_v4_keep(float* p, float4 v) {
    asm volatile(
        "{\n\t"
        ".reg .b64 pol;\n\t"
        "createpolicy.fractional.L2::evict_last.b64 pol, 1.0;\n\t"
        "red.global.add.L2::cache_hint.v4.f32 [%0], {%1,%2,%3,%4}, pol;\n\t"
        "}"
        :: "l"(p), "f"(v.x), "f"(v.y), "f"(v.z), "f"(v.w)
        : "memory");
}

// Streaming 32B copy with L2 evict_first (zero-reuse stream; keep L2 for the
// pview gather working set). ptxas requires .v4.b64 width for the modifier.
__device__ __forceinline__ ulonglong4 ld_stream32(const ulonglong4* p) {
    ulonglong4 v;
    asm volatile("ld.global.nc.L2::evict_first.v4.b64 {%0,%1,%2,%3}, [%4];"
                 : "=l"(v.x), "=l"(v.y), "=l"(v.z), "=l"(v.w) : "l"(p));
    return v;
}
__device__ __forceinline__ void st_stream32(ulonglong4* p, ulonglong4 v) {
    asm volatile("st.global.L2::evict_first.v4.b64 [%0], {%1,%2,%3,%4};"
                 :: "l"(p), "l"(v.x), "l"(v.y), "l"(v.z), "l"(v.w)
                 : "memory");
}

// One fused kernel, roles interleaved by blockIdx PARITY so every resident
// wave contains both streaming (BW-saturating) and gather (latency-bound)
// blocks — no sequential phases.
__global__ void __launch_bounds__(256) pp_fused_kernel(
    const int4*  __restrict__ coords,
    const float* __restrict__ pview,
    const ulonglong4* __restrict__ spatial32,
    ulonglong4* __restrict__ out32)
{
    const int tid = threadIdx.x;

    if ((blockIdx.x & 1) == 0) {
        // ---- copy path: 256MB out = spatial in 32B chunks, L2-bypassing ----
        int idx = (blockIdx.x >> 1) * 256 + tid;
        const int stride = COPY_BLOCKS * 256;          // 4194304
        #pragma unroll
        for (int i = 0; i < 2; i++) {
            st_stream32(out32 + idx, ld_stream32(spatial32 + idx));
            idx += stride;
        }
        return;
    }

    // ---- scatter path: 16 lanes per point, float4 per lane ----
    const int warp   = tid >> 5;
    const int half   = (tid >> 4) & 1;
    const int lane16 = tid & 15;
    const int pt = (blockIdx.x >> 1) * 16 + warp * 2 + half;

    int4 c = coords[pt];
    const int b = c.x, t = c.y, yy = c.z, xx = c.w;

    // Replicate reference f32 math exactly (no FMA contraction) so the
    // xf==0 special case matches bit-for-bit.
    float yf = __fadd_rn(__fmul_rn((float)yy, 0.2f), -51.2f);
    float xf = __fadd_rn(__fmul_rn((float)xx, 0.2f), -51.2f);

    float r = sqrtf(__fadd_rn(__fmul_rn(xf, xf), __fmul_rn(yf, yf)));
    float psi;
    if (xf == 0.0f && yf >= 0.0f) {
        psi = 1.57079632679489662f;       // pi/2
    } else {
        psi = atan2f(yf, xf);
    }

    float r_idx = __fdiv_rn(r, 0.3f);
    float p_idx = __fdiv_rn(__fadd_rn(psi, 3.14159265358979323846f),
                            0.012566370614359172f);

    int r0i = (int)floorf(r_idx);
    int p0i = (int)floorf(p_idx);
    // t frac is exactly 0 (integer cast to float) -> t+1 corner weight == 0.

    const float fr = r_idx - (float)r0i;
    const float fp = p_idx - (float)p0i;

    const int r0 = r0i * C_;
    const int r1 = min(r0i + 1, R_ - 1) * C_;
    const int p0 = p0i * RC_;
    const int p1 = min(p0i + 1, P_ - 1) * RC_;

    const float4* base = (const float4*)(pview + (b * T_ + t) * PRC_) + lane16;

    // Read-only NC gathers (coalesced 128B lines across the 16-lane group).
    float4 v00 = __ldg(base + (p0 + r0 >> 2));
    float4 v01 = __ldg(base + (p0 + r1 >> 2));
    float4 v10 = __ldg(base + (p1 + r0 >> 2));
    float4 v11 = __ldg(base + (p1 + r1 >> 2));

    const float wr0 = 1.0f - fr, wr1 = fr;
    const float wp0 = 1.0f - fp, wp1 = fp;

    float4 acc;
    acc.x = wp0 * (wr0 * v00.x + wr1 * v01.x) + wp1 * (wr0 * v10.x + wr1 * v11.x);
    acc.y = wp0 * (wr0 * v00.y + wr1 * v01.y) + wp1 * (wr0 * v10.y + wr1 * v11.y);
    acc.z = wp0 * (wr0 * v00.z + wr1 * v01.z) + wp1 * (wr0 * v10.z + wr1 * v11.z);
    acc.w = wp0 * (wr0 * v00.w + wr1 * v01.w) + wp1 * (wr0 * v10.w + wr1 * v11.w);

    // Coalesced fire-and-forget v4 reduction, pinned evict_last so the 2MB
    // scratch survives in L2 until the epilogue consumes it.
    float* dst = g_scratch + ((b * H_ + yy) * T_ + t) * C_ + 4 * lane16;
    red_add_v4_keep(dst, acc);
}

// Epilogue: one thread per (b, y, c) handles all 4 t values.
//  - scratch reads are L2 hits (pinned evict_last by the scatter reds)
//  - scratch is zeroed back in place (keeps the no-memset invariant)
//  - out update is fire-and-forget red.v4 (no dependent DRAM read)
__global__ void __launch_bounds__(256) pp_add_kernel(float* __restrict__ out)
{
    const int idx = blockIdx.x * 256 + threadIdx.x;  // (b, y, c) flat
    const int ch = idx & (C_ - 1);
    const int y  = (idx >> 6) & (H_ - 1);
    const int b  = idx >> 15;

    const int sbase = ((b * H_ + y) * T_) * C_ + ch;   // t stride = C_
    float v0 = g_scratch[sbase];
    float v1 = g_scratch[sbase + C_];
    float v2 = g_scratch[sbase + 2 * C_];
    float v3 = g_scratch[sbase + 3 * C_];

    g_scratch[sbase]          = 0.0f;
    g_scratch[sbase + C_]     = 0.0f;
    g_scratch[sbase + 2 * C_] = 0.0f;
    g_scratch[sbase + 3 * C_] = 0.0f;

    float4 v = make_float4(v0, v1, v2, v3);
    // out[b][ch][y][0..3] — 16B-aligned (base is a multiple of 512 floats)
    red_add_v4(out + b * (C_ * HW_) + ch * HW_ + y * W_, v);
}

extern "C" void kernel_launch(void* const* d_in, const int* in_sizes, int n_in,
                              void* d_out, int out_size) {
    const int*   coords  = (const int*)d_in[0];   // voxel_coords [N,4] int32
    const float* pview   = (const float*)d_in[1]; // [B,T,P,R,C] f32
    const float* spatial = (const float*)d_in[2]; // [B,C,H,W] f32
    float* out = (float*)d_out;

    pp_fused_kernel<<<COPY_BLOCKS + SCATTER_BLOCKS, 256>>>(
        (const int4*)coords, pview, (const ulonglong4*)spatial, (ulonglong4*)out);

    pp_add_kernel<<<(B_ * H_ * C_) / 256, 256>>>(out);
}

// round 16
// speedup vs baseline: 1.0824x; 1.0005x over previous
#include <cuda_runtime.h>
#include <math.h>

// Fixed shapes per reference
#define N_PTS 262144
#define B_ 4
#define T_ 4
#define P_ 512
#define R_ 256
#define C_ 64
#define H_ 512
#define W_ 512
#define HW_ (H_ * W_)
#define RC_ (R_ * C_)
#define PRC_ (P_ * RC_)

#define COPY_BLOCKS 16384
#define SCATTER_BLOCKS (N_PTS / 16)       // 16384: 16 points per 256-thr block
#define SCRATCH_ELEMS (B_ * H_ * T_ * C_) // 524288 floats (2MB, L2-resident)

// Privatized accumulator [b][y][t][c] (channel-contiguous -> coalesced REDs).
// BSS zero-init; epilogue re-zeros after consuming (invariant across replays).
__device__ float g_scratch[SCRATCH_ELEMS];

__device__ __forceinline__ void red_add_v4(float* p, float4 v) {
    asm volatile("red.global.add.v4.f32 [%0], {%1,%2,%3,%4};"
                 :: "l"(p), "f"(v.x), "f"(v.y), "f"(v.z), "f"(v.w)
                 : "memory");
}

// v4 reduction with L2 evict_last policy (pin scratch in L2 for the epilogue).
__device__ __forceinline__ void red_add_v4_keep(float* p, float4 v) {
    asm volatile(
        "{\n\t"
        ".reg .b64 pol;\n\t"
        "createpolicy.fractional.L2::evict_last.b64 pol, 1.0;\n\t"
        "red.global.add.L2::cache_hint.v4.f32 [%0], {%1,%2,%3,%4}, pol;\n\t"
        "}"
        :: "l"(p), "f"(v.x), "f"(v.y), "f"(v.z), "f"(v.w)
        : "memory");
}

// Streaming 32B copy with L2 evict_first (zero-reuse stream; keep L2 for the
// pview gather working set). ptxas requires .v4.b64 width for the modifier.
__device__ __forceinline__ ulonglong4 ld_stream32(const ulonglong4* p) {
    ulonglong4 v;
    asm volatile("ld.global.nc.L2::evict_first.v4.b64 {%0,%1,%2,%3}, [%4];"
                 : "=l"(v.x), "=l"(v.y), "=l"(v.z), "=l"(v.w) : "l"(p));
    return v;
}
__device__ __forceinline__ void st_stream32(ulonglong4* p, ulonglong4 v) {
    asm volatile("st.global.L2::evict_first.v4.b64 [%0], {%1,%2,%3,%4};"
                 :: "l"(p), "l"(v.x), "l"(v.y), "l"(v.z), "l"(v.w)
                 : "memory");
}

// One fused kernel, roles interleaved by blockIdx PARITY so every resident
// wave contains both streaming (BW-saturating) and gather (latency-bound)
// blocks. Each block triggers programmatic launch completion after its
// stores/reds so the PDL-launched epilogue can spin up under our tail.
__global__ void __launch_bounds__(256) pp_fused_kernel(
    const int4*  __restrict__ coords,
    const float* __restrict__ pview,
    const ulonglong4* __restrict__ spatial32,
    ulonglong4* __restrict__ out32)
{
    const int tid = threadIdx.x;

    if ((blockIdx.x & 1) == 0) {
        // ---- copy path: 256MB out = spatial in 32B chunks, L2-bypassing ----
        int idx = (blockIdx.x >> 1) * 256 + tid;
        const int stride = COPY_BLOCKS * 256;          // 4194304
        #pragma unroll
        for (int i = 0; i < 2; i++) {
            st_stream32(out32 + idx, ld_stream32(spatial32 + idx));
            idx += stride;
        }
        cudaTriggerProgrammaticLaunchCompletion();
        return;
    }

    // ---- scatter path: 16 lanes per point, float4 per lane ----
    const int warp   = tid >> 5;
    const int half   = (tid >> 4) & 1;
    const int lane16 = tid & 15;
    const int pt = (blockIdx.x >> 1) * 16 + warp * 2 + half;

    int4 c = coords[pt];
    const int b = c.x, t = c.y, yy = c.z, xx = c.w;

    // Replicate reference f32 math exactly (no FMA contraction) so the
    // xf==0 special case matches bit-for-bit.
    float yf = __fadd_rn(__fmul_rn((float)yy, 0.2f), -51.2f);
    float xf = __fadd_rn(__fmul_rn((float)xx, 0.2f), -51.2f);

    float r = sqrtf(__fadd_rn(__fmul_rn(xf, xf), __fmul_rn(yf, yf)));
    float psi;
    if (xf == 0.0f && yf >= 0.0f) {
        psi = 1.57079632679489662f;       // pi/2
    } else {
        psi = atan2f(yf, xf);
    }

    float r_idx = __fdiv_rn(r, 0.3f);
    float p_idx = __fdiv_rn(__fadd_rn(psi, 3.14159265358979323846f),
                            0.012566370614359172f);

    int r0i = (int)floorf(r_idx);
    int p0i = (int)floorf(p_idx);
    // t frac is exactly 0 (integer cast to float) -> t+1 corner weight == 0.

    const float fr = r_idx - (float)r0i;
    const float fp = p_idx - (float)p0i;

    const int r0 = r0i * C_;
    const int r1 = min(r0i + 1, R_ - 1) * C_;
    const int p0 = p0i * RC_;
    const int p1 = min(p0i + 1, P_ - 1) * RC_;

    const float4* base = (const float4*)(pview + (b * T_ + t) * PRC_) + lane16;

    // Read-only NC gathers (coalesced 128B lines across the 16-lane group).
    float4 v00 = __ldg(base + ((p0 + r0) >> 2));
    float4 v01 = __ldg(base + ((p0 + r1) >> 2));
    float4 v10 = __ldg(base + ((p1 + r0) >> 2));
    float4 v11 = __ldg(base + ((p1 + r1) >> 2));

    const float wr0 = 1.0f - fr, wr1 = fr;
    const float wp0 = 1.0f - fp, wp1 = fp;

    float4 acc;
    acc.x = wp0 * (wr0 * v00.x + wr1 * v01.x) + wp1 * (wr0 * v10.x + wr1 * v11.x);
    acc.y = wp0 * (wr0 * v00.y + wr1 * v01.y) + wp1 * (wr0 * v10.y + wr1 * v11.y);
    acc.z = wp0 * (wr0 * v00.z + wr1 * v01.z) + wp1 * (wr0 * v10.z + wr1 * v11.z);
    acc.w = wp0 * (wr0 * v00.w + wr1 * v01.w) + wp1 * (wr0 * v10.w + wr1 * v11.w);

    // Coalesced fire-and-forget v4 reduction, pinned evict_last so the 2MB
    // scratch survives in L2 until the epilogue consumes it.
    float* dst = g_scratch + ((b * H_ + yy) * T_ + t) * C_ + 4 * lane16;
    red_add_v4_keep(dst, acc);

    cudaTriggerProgrammaticLaunchCompletion();
}

// Epilogue (PDL secondary): blocks launch while the fused kernel drains; the
// index math runs in the shadow of the primary's tail, and
// cudaGridDependencySynchronize() guarantees all primary reds/stores are
// visible before the loads below.
__global__ void __launch_bounds__(256) pp_add_kernel(float* __restrict__ out)
{
    const int idx = blockIdx.x * 256 + threadIdx.x;  // (b, y, c) flat
    const int ch = idx & (C_ - 1);
    const int y  = (idx >> 6) & (H_ - 1);
    const int b  = idx >> 15;

    const int sbase = ((b * H_ + y) * T_) * C_ + ch;   // t stride = C_
    float* dst = out + b * (C_ * HW_) + ch * HW_ + y * W_;

    cudaGridDependencySynchronize();

    float v0 = g_scratch[sbase];
    float v1 = g_scratch[sbase + C_];
    float v2 = g_scratch[sbase + 2 * C_];
    float v3 = g_scratch[sbase + 3 * C_];

    g_scratch[sbase]          = 0.0f;
    g_scratch[sbase + C_]     = 0.0f;
    g_scratch[sbase + 2 * C_] = 0.0f;
    g_scratch[sbase + 3 * C_] = 0.0f;

    float4 v = make_float4(v0, v1, v2, v3);
    // out[b][ch][y][0..3] — 16B-aligned (base is a multiple of 512 floats)
    red_add_v4(dst, v);
}

extern "C" void kernel_launch(void* const* d_in, const int* in_sizes, int n_in,
                              void* d_out, int out_size) {
    const int*   coords  = (const int*)d_in[0];   // voxel_coords [N,4] int32
    const float* pview   = (const float*)d_in[1]; // [B,T,P,R,C] f32
    const float* spatial = (const float*)d_in[2]; // [B,C,H,W] f32
    float* out = (float*)d_out;

    pp_fused_kernel<<<COPY_BLOCKS + SCATTER_BLOCKS, 256>>>(
        (const int4*)coords, pview, (const ulonglong4*)spatial, (ulonglong4*)out);

    // PDL launch of the epilogue: overlaps its launch+prologue with the
    // primary's tail; griddepsync above provides the ordering.
    cudaLaunchConfig_t cfg = {};
    cfg.gridDim  = dim3((B_ * H_ * C_) / 256, 1, 1);
    cfg.blockDim = dim3(256, 1, 1);
    cfg.dynamicSmemBytes = 0;
    cfg.stream = 0;
    cudaLaunchAttribute attrs[1];
    attrs[0].id = cudaLaunchAttributeProgrammaticStreamSerialization;
    attrs[0].val.programmaticStreamSerializationAllowed = 1;
    cfg.attrs = attrs;
    cfg.numAttrs = 1;
    cudaLaunchKernelEx(&cfg, pp_add_kernel, out);
}